// round 6
// baseline (speedup 1.0000x reference)
#include <cuda_runtime.h>
#include <cstdint>

#define NX 256
#define NU 32
#define NY 32
#define BATCH 16
#define TLEN 8192
#define LCH 64
#define NCH (TLEN / LCH)   // 128
#define SUSTR 68           // suT row stride (floats): 16B-aligned, 4-way-conflict staging

typedef unsigned long long u64;

__device__ __forceinline__ u64 pk2(float lo, float hi) {
    u64 r; asm("mov.b64 %0,{%1,%2};" : "=l"(r) : "f"(lo), "f"(hi)); return r;
}
__device__ __forceinline__ void upk2(u64 v, float& lo, float& hi) {
    asm("mov.b64 {%0,%1},%2;" : "=f"(lo), "=f"(hi) : "l"(v));
}
__device__ __forceinline__ u64 ffma2(u64 a, u64 b, u64 c) {
    u64 d; asm("fma.rn.f32x2 %0,%1,%2,%3;" : "=l"(d) : "l"(a), "l"(b), "l"(c)); return d;
}

// Persistent scratch (small — no big V buffer anymore)
__device__ float g_Bz[NX * NU];     // [n][j] = (Q^T Bmat)
__device__ float g_CzT[NX * NY];    // [n][y] = (C Q)^T
__device__ float g_DT[NU * NY];     // [j][y] = D^T
__device__ float g_z0[BATCH * NX];
__device__ float g_lamL[NX];        // lam^64
__device__ float g_F[BATCH * NCH * NX];
__device__ float g_S[BATCH * NCH * NX];

// ---------------------------------------------------------------------------
// K0: prep — Bz, CzT, DT, z0, lam^64
// ---------------------------------------------------------------------------
__global__ void k_prep(const float* __restrict__ x0, const float* __restrict__ Q,
                       const float* __restrict__ lam, const float* __restrict__ Bm,
                       const float* __restrict__ Cin, const float* __restrict__ Dm) {
    int idx = blockIdx.x * blockDim.x + threadIdx.x;
    const int tBz = NX * NU;                 // 8192
    const int tCz = tBz + NY * NX;           // 16384
    const int tZ0 = tCz + BATCH * NX;        // 20480
    const int tLam = tZ0 + NX;               // 20736
    const int total = tLam + NU * NY;        // 21760
    for (; idx < total; idx += gridDim.x * blockDim.x) {
        if (idx < tBz) {
            int n = idx / NU, uu = idx % NU;
            float s = 0.f;
            #pragma unroll 8
            for (int k = 0; k < NX; k++) s = fmaf(Q[k * NX + n], Bm[k * NU + uu], s);
            g_Bz[idx] = s;
        } else if (idx < tCz) {
            int i = idx - tBz;
            int yy = i / NX, n = i % NX;
            float s = 0.f;
            #pragma unroll 8
            for (int k = 0; k < NX; k++) s = fmaf(Cin[yy * NX + k], Q[k * NX + n], s);
            g_CzT[n * NY + yy] = s;
        } else if (idx < tZ0) {
            int i = idx - tCz;
            int b = i / NX, n = i % NX;
            float s = 0.f;
            #pragma unroll 8
            for (int k = 0; k < NX; k++) s = fmaf(x0[b * NX + k], Q[k * NX + n], s);
            g_z0[i] = s;
        } else if (idx < tLam) {
            int n = idx - tZ0;
            float p = lam[n];
            #pragma unroll
            for (int j = 0; j < 6; j++) p = p * p;   // lam^64
            g_lamL[n] = p;
        } else {
            int i = idx - tLam;
            int j = i / NY, yy = i % NY;
            g_DT[i] = Dm[yy * NU + j];
        }
    }
}

// ---------------------------------------------------------------------------
// K1: per (b, chunk) — GEMM1 (v = Bz @ u) in registers, zero-init local scan,
//     emit chunk-final f. No v materialization.
// ---------------------------------------------------------------------------
__global__ void __launch_bounds__(256, 2) k_f(const float* __restrict__ u,
                                              const float* __restrict__ lam) {
    const int c = blockIdx.x, b = blockIdx.y, n = threadIdx.x;
    __shared__ __align__(16) float suT[NU * SUSTR];   // [j][t], 8.7 KB

    // Stage u transposed (no swizzle; GEMM1 reads are warp-broadcast)
    const float* ub = u + ((size_t)b * TLEN + (size_t)c * LCH) * NU;
    for (int i = n; i < LCH * NU / 4; i += 256) {
        float4 q = ((const float4*)ub)[i];
        int t = i >> 3, j0 = (i & 7) * 4;
        suT[(j0 + 0) * SUSTR + t] = q.x;
        suT[(j0 + 1) * SUSTR + t] = q.y;
        suT[(j0 + 2) * SUSTR + t] = q.z;
        suT[(j0 + 3) * SUSTR + t] = q.w;
    }

    float bz[NU];
    #pragma unroll
    for (int j = 0; j < NU; j++) bz[j] = g_Bz[n * NU + j];
    const float lamn = lam[n];
    __syncthreads();

    // GEMM1: acc[p] = {v_{2p}, v_{2p+1}} over all 64 t
    u64 acc[LCH / 2];
    #pragma unroll
    for (int p = 0; p < LCH / 2; p++) acc[p] = 0;

    #pragma unroll 4
    for (int j = 0; j < NU; j++) {
        u64 b2 = pk2(bz[j], bz[j]);
        const float* rp = &suT[j * SUSTR];
        #pragma unroll
        for (int p = 0; p < LCH / 2; p += 2) {
            ulonglong2 q = *(const ulonglong2*)(rp + 2 * p);
            acc[p]     = ffma2(b2, q.x, acc[p]);
            acc[p + 1] = ffma2(b2, q.y, acc[p + 1]);
        }
    }

    // Local scan (zero init; fold z0 for first chunk)
    float z = (c == 0) ? g_z0[b * NX + n] : 0.f;
    #pragma unroll
    for (int p = 0; p < LCH / 2; p++) {
        float lo, hi; upk2(acc[p], lo, hi);
        z = fmaf(lamn, z, lo);
        z = fmaf(lamn, z, hi);
    }
    g_F[(b * NCH + c) * NX + n] = z;
}

// ---------------------------------------------------------------------------
// K2: cross-chunk carry scan  S_0 = 0; S_c = lam^64 * S_{c-1} + f_{c-1}
// ---------------------------------------------------------------------------
__global__ void __launch_bounds__(256) k_carry() {
    const int b = blockIdx.x, n = threadIdx.x;
    const float lamLn = g_lamL[n];
    float s = 0.f;
    g_S[(b * NCH + 0) * NX + n] = 0.f;
    #pragma unroll 8
    for (int c = 1; c < NCH; c++) {
        s = fmaf(lamLn, s, g_F[(b * NCH + c - 1) * NX + n]);
        g_S[(b * NCH + c) * NX + n] = s;
    }
}

// ---------------------------------------------------------------------------
// K3: per (b, chunk) — recompute v (GEMM1), scan with true carry into smem,
//     GEMM2 (Cz + D fused) -> y
// ---------------------------------------------------------------------------
__global__ void __launch_bounds__(256, 2) k_y(const float* __restrict__ u,
                                              const float* __restrict__ lam,
                                              float* __restrict__ y) {
    extern __shared__ __align__(16) float sm[];
    float* zbuf = sm;                      // [n][t ^ ((n&7)<<2)]  NX*64 = 64 KB
    float* suT  = zbuf + NX * LCH;         // [j][t]  NU*SUSTR     = 8.7 KB
    float* sCz  = suT + NU * SUSTR;        // [n][y]  NX*NY        = 32 KB
    float* sDT  = sCz + NX * NY;           // [j][y]  NU*NY        = 4 KB

    const int c = blockIdx.x, b = blockIdx.y, tid = threadIdx.x;

    // Stage uT
    const float* ub = u + ((size_t)b * TLEN + (size_t)c * LCH) * NU;
    for (int i = tid; i < LCH * NU / 4; i += 256) {
        float4 q = ((const float4*)ub)[i];
        int t = i >> 3, j0 = (i & 7) * 4;
        suT[(j0 + 0) * SUSTR + t] = q.x;
        suT[(j0 + 1) * SUSTR + t] = q.y;
        suT[(j0 + 2) * SUSTR + t] = q.z;
        suT[(j0 + 3) * SUSTR + t] = q.w;
    }
    // Stage Cz^T and D^T
    for (int i = tid; i < NX * NY / 4; i += 256)
        ((float4*)sCz)[i] = ((const float4*)g_CzT)[i];
    for (int i = tid; i < NU * NY / 4; i += 256)
        ((float4*)sDT)[i] = ((const float4*)g_DT)[i];

    // Per-thread state for GEMM1 + scan (thread = n)
    const int n = tid;
    float bz[NU];
    #pragma unroll
    for (int j = 0; j < NU; j++) bz[j] = g_Bz[n * NU + j];
    const float lamn = lam[n];
    float z = (c == 0) ? g_z0[b * NX + n] : g_S[(b * NCH + c) * NX + n];
    const int sw = (n & 7) << 2;
    float* zrow = zbuf + n * LCH;
    __syncthreads();

    // Two halves of 32 t: GEMM1 into 16 u64 accs, then scan into zbuf
    #pragma unroll
    for (int h = 0; h < 2; h++) {
        const int tb = h * 32;
        u64 acc[16];
        #pragma unroll
        for (int p = 0; p < 16; p++) acc[p] = 0;

        #pragma unroll 4
        for (int j = 0; j < NU; j++) {
            u64 b2 = pk2(bz[j], bz[j]);
            const float* rp = &suT[j * SUSTR + tb];
            #pragma unroll
            for (int p = 0; p < 16; p += 2) {
                ulonglong2 q = *(const ulonglong2*)(rp + 2 * p);
                acc[p]     = ffma2(b2, q.x, acc[p]);
                acc[p + 1] = ffma2(b2, q.y, acc[p + 1]);
            }
        }
        // Scan: store z_prev (state BEFORE update) for each t
        #pragma unroll
        for (int p = 0; p < 16; p++) {
            float lo, hi; upk2(acc[p], lo, hi);
            int t = tb + 2 * p;
            zrow[t ^ sw] = z;
            z = fmaf(lamn, z, lo);
            zrow[(t + 1) ^ sw] = z;
            z = fmaf(lamn, z, hi);
        }
    }
    __syncthreads();

    // GEMM2: warp w owns t = w*8 .. w*8+7, lane = y
    const int w = tid >> 5, lane = tid & 31;
    const int t0 = w * 8;

    u64 a2[4] = {0, 0, 0, 0};   // pairs (t0,t0+1)...(t0+6,t0+7)

    #pragma unroll 2
    for (int nn = 0; nn < NX; nn++) {
        float cv = sCz[nn * NY + lane];
        u64 c2 = pk2(cv, cv);
        const int s2 = (nn & 7) << 2;
        const float* zr = zbuf + nn * LCH;
        ulonglong2 qa = *(const ulonglong2*)(zr + (t0 ^ s2));
        ulonglong2 qb = *(const ulonglong2*)(zr + ((t0 + 4) ^ s2));
        a2[0] = ffma2(c2, qa.x, a2[0]);
        a2[1] = ffma2(c2, qa.y, a2[1]);
        a2[2] = ffma2(c2, qb.x, a2[2]);
        a2[3] = ffma2(c2, qb.y, a2[3]);
    }
    #pragma unroll
    for (int j = 0; j < NU; j++) {
        float dv = sDT[j * NY + lane];
        u64 d2 = pk2(dv, dv);
        const float* ur = suT + j * SUSTR + t0;
        ulonglong2 qa = *(const ulonglong2*)(ur);
        ulonglong2 qb = *(const ulonglong2*)(ur + 4);
        a2[0] = ffma2(d2, qa.x, a2[0]);
        a2[1] = ffma2(d2, qa.y, a2[1]);
        a2[2] = ffma2(d2, qb.x, a2[2]);
        a2[3] = ffma2(d2, qb.y, a2[3]);
    }

    float* yb = y + ((size_t)(b * TLEN + c * LCH + t0)) * NY + lane;
    #pragma unroll
    for (int g = 0; g < 4; g++) {
        float o0, o1; upk2(a2[g], o0, o1);
        yb[(size_t)(2 * g) * NY] = o0;
        yb[(size_t)(2 * g + 1) * NY] = o1;
    }
}

// ---------------------------------------------------------------------------
extern "C" void kernel_launch(void* const* d_in, const int* in_sizes, int n_in,
                              void* d_out, int out_size) {
    const float* x0  = (const float*)d_in[0];
    const float* u   = (const float*)d_in[1];
    const float* Q   = (const float*)d_in[2];
    const float* lam = (const float*)d_in[3];
    const float* Bm  = (const float*)d_in[4];
    const float* Cin = (const float*)d_in[5];
    const float* Dm  = (const float*)d_in[6];
    float* y = (float*)d_out;

    const int smem_k3 = (NX * LCH + NU * SUSTR + NX * NY + NU * NY) * 4;  // 110 KB
    cudaFuncSetAttribute(k_y, cudaFuncAttributeMaxDynamicSharedMemorySize, smem_k3);

    k_prep<<<85, 256>>>(x0, Q, lam, Bm, Cin, Dm);
    k_f<<<dim3(NCH, BATCH), 256>>>(u, lam);
    k_carry<<<BATCH, 256>>>();
    k_y<<<dim3(NCH, BATCH), 256, smem_k3>>>(u, lam, y);
}

// round 8
// speedup vs baseline: 1.0531x; 1.0531x over previous
#include <cuda_runtime.h>
#include <cstdint>

#define NX 256
#define NU 32
#define NY 32
#define BATCH 16
#define TLEN 8192
#define LCH 64
#define NCH (TLEN / LCH)   // 128
#define SUSTR 68           // suT row stride (floats): 16B-aligned, 4-way-conflict staging

typedef unsigned long long u64;

__device__ __forceinline__ u64 pk2(float lo, float hi) {
    u64 r; asm("mov.b64 %0,{%1,%2};" : "=l"(r) : "f"(lo), "f"(hi)); return r;
}
__device__ __forceinline__ void upk2(u64 v, float& lo, float& hi) {
    asm("mov.b64 {%0,%1},%2;" : "=f"(lo), "=f"(hi) : "l"(v));
}
__device__ __forceinline__ u64 ffma2(u64 a, u64 b, u64 c) {
    u64 d; asm("fma.rn.f32x2 %0,%1,%2,%3;" : "=l"(d) : "l"(a), "l"(b), "l"(c)); return d;
}

// Persistent scratch (small — no big V buffer anymore)
__device__ float g_Bz[NX * NU];     // [n][j] = (Q^T Bmat)
__device__ float g_CzT[NX * NY];    // [n][y] = (C Q)^T
__device__ float g_DT[NU * NY];     // [j][y] = D^T
__device__ float g_z0[BATCH * NX];
__device__ float g_lamL[NX];        // lam^64
__device__ float g_F[BATCH * NCH * NX];
__device__ float g_S[BATCH * NCH * NX];

// ---------------------------------------------------------------------------
// K0: prep — Bz, CzT, DT, z0, lam^64
// ---------------------------------------------------------------------------
__global__ void k_prep(const float* __restrict__ x0, const float* __restrict__ Q,
                       const float* __restrict__ lam, const float* __restrict__ Bm,
                       const float* __restrict__ Cin, const float* __restrict__ Dm) {
    int idx = blockIdx.x * blockDim.x + threadIdx.x;
    const int tBz = NX * NU;                 // 8192
    const int tCz = tBz + NY * NX;           // 16384
    const int tZ0 = tCz + BATCH * NX;        // 20480
    const int tLam = tZ0 + NX;               // 20736
    const int total = tLam + NU * NY;        // 21760
    for (; idx < total; idx += gridDim.x * blockDim.x) {
        if (idx < tBz) {
            int n = idx / NU, uu = idx % NU;
            float s = 0.f;
            #pragma unroll 8
            for (int k = 0; k < NX; k++) s = fmaf(Q[k * NX + n], Bm[k * NU + uu], s);
            g_Bz[idx] = s;
        } else if (idx < tCz) {
            int i = idx - tBz;
            int yy = i / NX, n = i % NX;
            float s = 0.f;
            #pragma unroll 8
            for (int k = 0; k < NX; k++) s = fmaf(Cin[yy * NX + k], Q[k * NX + n], s);
            g_CzT[n * NY + yy] = s;
        } else if (idx < tZ0) {
            int i = idx - tCz;
            int b = i / NX, n = i % NX;
            float s = 0.f;
            #pragma unroll 8
            for (int k = 0; k < NX; k++) s = fmaf(x0[b * NX + k], Q[k * NX + n], s);
            g_z0[i] = s;
        } else if (idx < tLam) {
            int n = idx - tZ0;
            float p = lam[n];
            #pragma unroll
            for (int j = 0; j < 6; j++) p = p * p;   // lam^64
            g_lamL[n] = p;
        } else {
            int i = idx - tLam;
            int j = i / NY, yy = i % NY;
            g_DT[i] = Dm[yy * NU + j];
        }
    }
}

// ---------------------------------------------------------------------------
// K1: per (b, chunk) — GEMM1 (v = Bz @ u) in registers, zero-init local scan,
//     emit chunk-final f. No v materialization.
// ---------------------------------------------------------------------------
__global__ void __launch_bounds__(256, 2) k_f(const float* __restrict__ u,
                                              const float* __restrict__ lam) {
    const int c = blockIdx.x, b = blockIdx.y, n = threadIdx.x;
    __shared__ __align__(16) float suT[NU * SUSTR];   // [j][t], 8.7 KB

    // Stage u transposed (no swizzle; GEMM1 reads are warp-broadcast)
    const float* ub = u + ((size_t)b * TLEN + (size_t)c * LCH) * NU;
    for (int i = n; i < LCH * NU / 4; i += 256) {
        float4 q = ((const float4*)ub)[i];
        int t = i >> 3, j0 = (i & 7) * 4;
        suT[(j0 + 0) * SUSTR + t] = q.x;
        suT[(j0 + 1) * SUSTR + t] = q.y;
        suT[(j0 + 2) * SUSTR + t] = q.z;
        suT[(j0 + 3) * SUSTR + t] = q.w;
    }

    float bz[NU];
    #pragma unroll
    for (int j = 0; j < NU; j++) bz[j] = g_Bz[n * NU + j];
    const float lamn = lam[n];
    __syncthreads();

    // GEMM1: acc[p] = {v_{2p}, v_{2p+1}} over all 64 t
    u64 acc[LCH / 2];
    #pragma unroll
    for (int p = 0; p < LCH / 2; p++) acc[p] = 0;

    #pragma unroll 4
    for (int j = 0; j < NU; j++) {
        u64 b2 = pk2(bz[j], bz[j]);
        const float* rp = &suT[j * SUSTR];
        #pragma unroll
        for (int p = 0; p < LCH / 2; p += 2) {
            ulonglong2 q = *(const ulonglong2*)(rp + 2 * p);
            acc[p]     = ffma2(b2, q.x, acc[p]);
            acc[p + 1] = ffma2(b2, q.y, acc[p + 1]);
        }
    }

    // Local scan (zero init; fold z0 for first chunk)
    float z = (c == 0) ? g_z0[b * NX + n] : 0.f;
    #pragma unroll
    for (int p = 0; p < LCH / 2; p++) {
        float lo, hi; upk2(acc[p], lo, hi);
        z = fmaf(lamn, z, lo);
        z = fmaf(lamn, z, hi);
    }
    g_F[(b * NCH + c) * NX + n] = z;
}

// ---------------------------------------------------------------------------
// K2: cross-chunk carry scan  S_0 = 0; S_c = lam^64 * S_{c-1} + f_{c-1}
// ---------------------------------------------------------------------------
__global__ void __launch_bounds__(256) k_carry() {
    const int b = blockIdx.x, n = threadIdx.x;
    const float lamLn = g_lamL[n];
    float s = 0.f;
    g_S[(b * NCH + 0) * NX + n] = 0.f;
    #pragma unroll 8
    for (int c = 1; c < NCH; c++) {
        s = fmaf(lamLn, s, g_F[(b * NCH + c - 1) * NX + n]);
        g_S[(b * NCH + c) * NX + n] = s;
    }
}

// ---------------------------------------------------------------------------
// K3: per (b, chunk) — recompute v (GEMM1), scan with true carry into smem,
//     GEMM2 (Cz + D fused) -> y
// ---------------------------------------------------------------------------
__global__ void __launch_bounds__(256, 2) k_y(const float* __restrict__ u,
                                              const float* __restrict__ lam,
                                              float* __restrict__ y) {
    extern __shared__ __align__(16) float sm[];
    float* zbuf = sm;                      // [n][t ^ ((n&7)<<2)]  NX*64 = 64 KB
    float* suT  = zbuf + NX * LCH;         // [j][t]  NU*SUSTR     = 8.7 KB
    float* sCz  = suT + NU * SUSTR;        // [n][y]  NX*NY        = 32 KB
    float* sDT  = sCz + NX * NY;           // [j][y]  NU*NY        = 4 KB

    const int c = blockIdx.x, b = blockIdx.y, tid = threadIdx.x;

    // Stage uT
    const float* ub = u + ((size_t)b * TLEN + (size_t)c * LCH) * NU;
    for (int i = tid; i < LCH * NU / 4; i += 256) {
        float4 q = ((const float4*)ub)[i];
        int t = i >> 3, j0 = (i & 7) * 4;
        suT[(j0 + 0) * SUSTR + t] = q.x;
        suT[(j0 + 1) * SUSTR + t] = q.y;
        suT[(j0 + 2) * SUSTR + t] = q.z;
        suT[(j0 + 3) * SUSTR + t] = q.w;
    }
    // Stage Cz^T and D^T
    for (int i = tid; i < NX * NY / 4; i += 256)
        ((float4*)sCz)[i] = ((const float4*)g_CzT)[i];
    for (int i = tid; i < NU * NY / 4; i += 256)
        ((float4*)sDT)[i] = ((const float4*)g_DT)[i];

    // Per-thread state for GEMM1 + scan (thread = n)
    const int n = tid;
    float bz[NU];
    #pragma unroll
    for (int j = 0; j < NU; j++) bz[j] = g_Bz[n * NU + j];
    const float lamn = lam[n];
    float z = (c == 0) ? g_z0[b * NX + n] : g_S[(b * NCH + c) * NX + n];
    const int sw = (n & 7) << 2;
    float* zrow = zbuf + n * LCH;
    __syncthreads();

    // Two halves of 32 t: GEMM1 into 16 u64 accs, then scan into zbuf
    #pragma unroll
    for (int h = 0; h < 2; h++) {
        const int tb = h * 32;
        u64 acc[16];
        #pragma unroll
        for (int p = 0; p < 16; p++) acc[p] = 0;

        #pragma unroll 4
        for (int j = 0; j < NU; j++) {
            u64 b2 = pk2(bz[j], bz[j]);
            const float* rp = &suT[j * SUSTR + tb];
            #pragma unroll
            for (int p = 0; p < 16; p += 2) {
                ulonglong2 q = *(const ulonglong2*)(rp + 2 * p);
                acc[p]     = ffma2(b2, q.x, acc[p]);
                acc[p + 1] = ffma2(b2, q.y, acc[p + 1]);
            }
        }
        // Scan: store z_prev (state BEFORE update) for each t
        #pragma unroll
        for (int p = 0; p < 16; p++) {
            float lo, hi; upk2(acc[p], lo, hi);
            int t = tb + 2 * p;
            zrow[t ^ sw] = z;
            z = fmaf(lamn, z, lo);
            zrow[(t + 1) ^ sw] = z;
            z = fmaf(lamn, z, hi);
        }
    }
    __syncthreads();

    // GEMM2: warp w owns t = w*8 .. w*8+7, lane = y
    const int w = tid >> 5, lane = tid & 31;
    const int t0 = w * 8;

    u64 a2[4] = {0, 0, 0, 0};   // pairs (t0,t0+1)...(t0+6,t0+7)

    #pragma unroll 2
    for (int nn = 0; nn < NX; nn++) {
        float cv = sCz[nn * NY + lane];
        u64 c2 = pk2(cv, cv);
        const int s2 = (nn & 7) << 2;
        const float* zr = zbuf + nn * LCH;
        ulonglong2 qa = *(const ulonglong2*)(zr + (t0 ^ s2));
        ulonglong2 qb = *(const ulonglong2*)(zr + ((t0 + 4) ^ s2));
        a2[0] = ffma2(c2, qa.x, a2[0]);
        a2[1] = ffma2(c2, qa.y, a2[1]);
        a2[2] = ffma2(c2, qb.x, a2[2]);
        a2[3] = ffma2(c2, qb.y, a2[3]);
    }
    #pragma unroll
    for (int j = 0; j < NU; j++) {
        float dv = sDT[j * NY + lane];
        u64 d2 = pk2(dv, dv);
        const float* ur = suT + j * SUSTR + t0;
        ulonglong2 qa = *(const ulonglong2*)(ur);
        ulonglong2 qb = *(const ulonglong2*)(ur + 4);
        a2[0] = ffma2(d2, qa.x, a2[0]);
        a2[1] = ffma2(d2, qa.y, a2[1]);
        a2[2] = ffma2(d2, qb.x, a2[2]);
        a2[3] = ffma2(d2, qb.y, a2[3]);
    }

    float* yb = y + ((size_t)(b * TLEN + c * LCH + t0)) * NY + lane;
    #pragma unroll
    for (int g = 0; g < 4; g++) {
        float o0, o1; upk2(a2[g], o0, o1);
        yb[(size_t)(2 * g) * NY] = o0;
        yb[(size_t)(2 * g + 1) * NY] = o1;
    }
}

// ---------------------------------------------------------------------------
extern "C" void kernel_launch(void* const* d_in, const int* in_sizes, int n_in,
                              void* d_out, int out_size) {
    const float* x0  = (const float*)d_in[0];
    const float* u   = (const float*)d_in[1];
    const float* Q   = (const float*)d_in[2];
    const float* lam = (const float*)d_in[3];
    const float* Bm  = (const float*)d_in[4];
    const float* Cin = (const float*)d_in[5];
    const float* Dm  = (const float*)d_in[6];
    float* y = (float*)d_out;

    const int smem_k3 = (NX * LCH + NU * SUSTR + NX * NY + NU * NY) * 4;  // 110 KB
    cudaFuncSetAttribute(k_y, cudaFuncAttributeMaxDynamicSharedMemorySize, smem_k3);

    k_prep<<<85, 256>>>(x0, Q, lam, Bm, Cin, Dm);
    k_f<<<dim3(NCH, BATCH), 256>>>(u, lam);
    k_carry<<<BATCH, 256>>>();
    k_y<<<dim3(NCH, BATCH), 256, smem_k3>>>(u, lam, y);
}